// round 13
// baseline (speedup 1.0000x reference)
#include <cuda_runtime.h>
#include <cuda_fp16.h>
#include <stdint.h>

#define SEQL 2048
#define NB   4
#define DM   768
#define MTOT (NB*SEQL)

#define TM 128
#define TN 128
#define BK 32
#define NTHR 128
#define SAH   40
#define SBNTH 40
#define SBNNH 136
#define STAGES 4
#define AS_BYTES (TM*SAH*2)
#define BS_BYTES (TN*SBNTH*2)
#define STAGE_BYTES (AS_BYTES + BS_BYTES)
#define SMEM_TOTAL (STAGES*STAGE_BYTES)   // 81920

#define NMT (SEQL/TM)    // 16 m-tiles per batch

__device__ __half g_X[(size_t)MTOT*DM];
__device__ __half g_W[(size_t)3*DM*DM];
__device__ __half g_Q[(size_t)MTOT*DM];
__device__ __half g_K[(size_t)MTOT*DM];
__device__ __half g_V[(size_t)MTOT*DM];
__device__ __half g_P[(size_t)NB*SEQL*SEQL];
__device__ float  g_PS[(size_t)NB*NMT*NMT*2*128];

static __device__ __forceinline__ void cp16(uint32_t s, const void* g){
    asm volatile("cp.async.cg.shared.global [%0], [%1], 16;" :: "r"(s), "l"(g) : "memory");
}
static __device__ __forceinline__ void ldsm4(uint32_t r[4], uint32_t a){
    asm volatile("ldmatrix.sync.aligned.m8n8.x4.shared.b16 {%0,%1,%2,%3}, [%4];"
        : "=r"(r[0]),"=r"(r[1]),"=r"(r[2]),"=r"(r[3]) : "r"(a));
}
static __device__ __forceinline__ void ldsm4t(uint32_t r[4], uint32_t a){
    asm volatile("ldmatrix.sync.aligned.m8n8.x4.trans.shared.b16 {%0,%1,%2,%3}, [%4];"
        : "=r"(r[0]),"=r"(r[1]),"=r"(r[2]),"=r"(r[3]) : "r"(a));
}
static __device__ __forceinline__ void mma16(float d[4], const uint32_t a[4], uint32_t b0, uint32_t b1){
    asm volatile("mma.sync.aligned.m16n8k16.row.col.f32.f16.f16.f32 "
        "{%0,%1,%2,%3}, {%4,%5,%6,%7}, {%8,%9}, {%0,%1,%2,%3};"
        : "+f"(d[0]),"+f"(d[1]),"+f"(d[2]),"+f"(d[3])
        : "r"(a[0]),"r"(a[1]),"r"(a[2]),"r"(a[3]),"r"(b0),"r"(b1));
}

// ---------------------------------------------------------------------------
template<bool BNT>
static __device__ __forceinline__ void gemm_run(
    const __half* __restrict__ A, int lda,
    const __half* __restrict__ B, int ldb,
    int kT, float C[4][8][4])
{
    extern __shared__ char smx[];
    const uint32_t sbase = (uint32_t)__cvta_generic_to_shared(smx);
    const int t = threadIdx.x, lane = t & 31, wid = t >> 5;
    const int wm = (wid & 1) * 64, wn = (wid >> 1) * 64;
    const int lrow = (lane & 7) + ((lane >> 3) & 1) * 8;
    const int loct = lane >> 4;
    const int nIt = kT / BK;

    auto issue = [&](int c){
        const int buf = c & (STAGES-1);
        const uint32_t ab = sbase + buf*STAGE_BYTES;
        const uint32_t bb = ab + AS_BYTES;
        const int k0 = c * BK;
        #pragma unroll
        for (int i=0;i<4;i++){
            int f = t + i*NTHR, row = f>>2, seg = f&3;
            cp16(ab + row*(SAH*2) + seg*16, A + (size_t)row*lda + k0 + seg*8);
        }
        #pragma unroll
        for (int i=0;i<4;i++){
            int f = t + i*NTHR;
            if (BNT){
                int row = f>>2, seg = f&3;
                cp16(bb + row*(SBNTH*2) + seg*16, B + (size_t)row*ldb + k0 + seg*8);
            } else {
                int row = f>>4, seg = f&15;
                cp16(bb + row*(SBNNH*2) + seg*16, B + (size_t)(k0+row)*ldb + seg*8);
            }
        }
        asm volatile("cp.async.commit_group;" ::: "memory");
    };

    #pragma unroll
    for (int s=0; s<STAGES-1; s++) issue(s);

    for (int it=0; it<nIt; it++){
        asm volatile("cp.async.wait_group %0;" :: "n"(STAGES-2) : "memory");
        __syncthreads();
        if (it + STAGES-1 < nIt) issue(it + STAGES-1);
        else asm volatile("cp.async.commit_group;" ::: "memory");

        const uint32_t as = sbase + (it & (STAGES-1))*STAGE_BYTES;
        const uint32_t bs = as + AS_BYTES;

        uint32_t af[2][4][4], bf[2][4][4];
        auto ldA = [&](uint32_t f[4][4], int ks){
            #pragma unroll
            for (int mt=0; mt<4; mt++)
                ldsm4(f[mt], as + (wm + mt*16 + lrow)*(SAH*2) + (ks*16 + loct*8)*2);
        };
        auto ldB = [&](uint32_t f[4][4], int ks){
            #pragma unroll
            for (int n2=0; n2<4; n2++){
                if (BNT)
                    ldsm4(f[n2], bs + (wn + n2*16 + lrow)*(SBNTH*2) + (ks*16 + loct*8)*2);
                else
                    ldsm4t(f[n2], bs + (ks*16 + lrow)*(SBNNH*2) + (wn + n2*16 + loct*8)*2);
            }
        };

        ldA(af[0], 0); ldB(bf[0], 0);
        #pragma unroll
        for (int ks=0; ks<2; ks++){
            if (ks == 0){ ldA(af[1], 1); ldB(bf[1], 1); }
            #pragma unroll
            for (int mt=0; mt<4; mt++)
                #pragma unroll
                for (int nt=0; nt<8; nt++){
                    const int n2 = nt>>1, od = nt&1;
                    uint32_t b0 = BNT ? bf[ks][n2][od]   : bf[ks][n2][od*2];
                    uint32_t b1 = BNT ? bf[ks][n2][2+od] : bf[ks][n2][od*2+1];
                    mma16(C[mt][nt], af[ks][mt], b0, b1);
                }
        }
    }
}

static __device__ __forceinline__ void epilogue_h(__half* D, int ldd, float C[4][8][4], float scale)
{
    const int lane = threadIdx.x & 31, wid = threadIdx.x >> 5;
    const int g = lane>>2, tg = lane&3;
    const int wm = (wid&1)*64, wn = (wid>>1)*64;
    #pragma unroll
    for (int mt=0; mt<4; mt++)
        #pragma unroll
        for (int nt=0; nt<8; nt++){
            const int r0 = wm+mt*16+g, c0 = wn+nt*8+2*tg;
            __half2 v0 = __floats2half2_rn(C[mt][nt][0]*scale, C[mt][nt][1]*scale);
            __half2 v1 = __floats2half2_rn(C[mt][nt][2]*scale, C[mt][nt][3]*scale);
            *(__half2*)&D[(size_t)r0*ldd + c0]     = v0;
            *(__half2*)&D[(size_t)(r0+8)*ldd + c0] = v1;
        }
}

static __device__ __forceinline__ void epilogue_p(
    __half* D, int ldd, float C[4][8][4], bool diag, float* __restrict__ psum)
{
    const int lane = threadIdx.x & 31, wid = threadIdx.x >> 5;
    const int g = lane>>2, tg = lane&3;
    const int wm = (wid&1)*64, wn = (wid>>1)*64;
    float rs[4][2] = {};
    #pragma unroll
    for (int mt=0; mt<4; mt++)
        #pragma unroll
        for (int nt=0; nt<8; nt++){
            const int r0 = wm+mt*16+g, c0 = wn+nt*8+2*tg;
            float e0 = __expf(C[mt][nt][0]), e1 = __expf(C[mt][nt][1]);
            float e2 = __expf(C[mt][nt][2]), e3 = __expf(C[mt][nt][3]);
            if (diag){
                if (c0   > r0  ) e0 = 0.0f;
                if (c0+1 > r0  ) e1 = 0.0f;
                if (c0   > r0+8) e2 = 0.0f;
                if (c0+1 > r0+8) e3 = 0.0f;
            }
            *(__half2*)&D[(size_t)r0*ldd + c0]     = __floats2half2_rn(e0, e1);
            *(__half2*)&D[(size_t)(r0+8)*ldd + c0] = __floats2half2_rn(e2, e3);
            rs[mt][0] += e0 + e1;
            rs[mt][1] += e2 + e3;
        }
    #pragma unroll
    for (int mt=0; mt<4; mt++)
        #pragma unroll
        for (int h=0; h<2; h++){
            float v = rs[mt][h];
            v += __shfl_xor_sync(0xffffffffu, v, 1);
            v += __shfl_xor_sync(0xffffffffu, v, 2);
            if (tg == 0)
                psum[(wid>>1)*128 + wm + mt*16 + h*8 + g] = v;
        }
}

static __device__ __forceinline__ void epilogue_fs(float* D, int ldd, float C[4][8][4],
                                                   const float* __restrict__ sInv)
{
    const int lane = threadIdx.x & 31, wid = threadIdx.x >> 5;
    const int g = lane>>2, tg = lane&3;
    const int wm = (wid&1)*64, wn = (wid>>1)*64;
    #pragma unroll
    for (int mt=0; mt<4; mt++){
        const float iv0 = sInv[wm+mt*16+g], iv1 = sInv[wm+mt*16+g+8];
        #pragma unroll
        for (int nt=0; nt<8; nt++){
            const int r0 = wm+mt*16+g, c0 = wn+nt*8+2*tg;
            *(float2*)&D[(size_t)r0*ldd + c0]     = make_float2(C[mt][nt][0]*iv0, C[mt][nt][1]*iv0);
            *(float2*)&D[(size_t)(r0+8)*ldd + c0] = make_float2(C[mt][nt][2]*iv1, C[mt][nt][3]*iv1);
        }
    }
}

// ---------------------------------------------------------------------------
__global__ void __launch_bounds__(256) cvt_k(
    const float4* __restrict__ x, const float4* __restrict__ Wq,
    const float4* __restrict__ Wk, const float4* __restrict__ Wv)
{
    const int nx4 = MTOT*DM/4, nw4 = DM*DM/4;
    int i = blockIdx.x*256 + threadIdx.x;
    const float4* src; __half* dst; int idx;
    if (i < nx4){ src = x; dst = g_X; idx = i; }
    else {
        int j = i - nx4;
        int w = j / nw4; idx = j - w*nw4;
        src = (w==0) ? Wq : (w==1) ? Wk : Wv;
        dst = g_W + (size_t)w*DM*DM;
    }
    float4 v = src[idx];
    __half2 h0 = __floats2half2_rn(v.x, v.y);
    __half2 h1 = __floats2half2_rn(v.z, v.w);
    ((uint2*)dst)[idx] = make_uint2(*(uint32_t*)&h0, *(uint32_t*)&h1);
}

// Q and K projections only (z = 0,1)
__global__ void __launch_bounds__(NTHR,2) qk_k()
{
    const int m0 = blockIdx.y*TM, n0 = blockIdx.x*TN;
    const __half* W = g_W + (size_t)blockIdx.z*DM*DM;
    __half*      Cd = (blockIdx.z==0) ? g_Q : g_K;
    const float scale = (blockIdx.z==0) ? rsqrtf((float)DM) : 1.0f;

    float C[4][8][4] = {};
    gemm_run<true>(g_X + (size_t)m0*DM, DM, W + (size_t)n0*DM, DM, DM, C);
    epilogue_h(Cd + (size_t)m0*DM + n0, DM, C, scale);
}

// V projection (runs on side stream, overlapped with scores_k)
__global__ void __launch_bounds__(NTHR,2) v_k()
{
    const int m0 = blockIdx.y*TM, n0 = blockIdx.x*TN;
    const __half* W = g_W + (size_t)2*DM*DM;

    float C[4][8][4] = {};
    gemm_run<true>(g_X + (size_t)m0*DM, DM, W + (size_t)n0*DM, DM, DM, C);
    epilogue_h(g_V + (size_t)m0*DM + n0, DM, C, 1.0f);
}

__global__ void __launch_bounds__(NTHR,2) scores_k()
{
    const int b = blockIdx.y;
    int i = blockIdx.x;
    int m = (int)((sqrtf(8.0f*i + 1.0f) - 1.0f) * 0.5f);
    while ((m+1)*(m+2)/2 <= i) ++m;
    while (m*(m+1)/2 > i) --m;
    const int n = i - m*(m+1)/2;
    const int m0 = m*TM, n0 = n*TN;

    float C[4][8][4] = {};
    gemm_run<true>(g_Q + ((size_t)b*SEQL + m0)*DM, DM,
                   g_K + ((size_t)b*SEQL + n0)*DM, DM, DM, C);
    epilogue_p(g_P + (size_t)b*SEQL*SEQL + (size_t)m0*SEQL + n0, SEQL, C,
               (m == n),
               g_PS + ((size_t)(b*NMT + m)*NMT + n)*256);
}

__global__ void __launch_bounds__(NTHR,2) out_k(float* __restrict__ out)
{
    const int y = blockIdx.y;
    const int mt = NMT - 1 - (y >> 2);     // largest K first, across batches
    const int b  = y & 3;
    const int m0 = mt*TM, n0 = blockIdx.x*TN;

    __shared__ float sInv[128];
    {
        const int r = threadIdx.x;
        const float* ps = g_PS + (size_t)(b*NMT + mt)*NMT*256;
        float s = 0.0f;
        for (int nt=0; nt<=mt; nt++)
            s += ps[nt*256 + r] + ps[nt*256 + 128 + r];
        sInv[r] = 1.0f / s;
    }
    __syncthreads();

    float C[4][8][4] = {};
    gemm_run<false>(g_P + (size_t)b*SEQL*SEQL + (size_t)m0*SEQL, SEQL,
                    g_V + (size_t)b*SEQL*DM + n0, DM, m0 + TM, C);
    epilogue_fs(out + ((size_t)b*SEQL + m0)*DM + n0, DM, C, sInv);
}

// ---------------------------------------------------------------------------
extern "C" void kernel_launch(void* const* d_in, const int* in_sizes, int n_in,
                              void* d_out, int out_size)
{
    const float* x  = (const float*)d_in[0];
    const float* Wq = (const float*)d_in[1];
    const float* Wk = (const float*)d_in[2];
    const float* Wv = (const float*)d_in[3];
    float* out = (float*)d_out;

    static int inited = 0;
    static cudaStream_t s2;
    static cudaEvent_t eFork, eJoin;
    if (!inited){
        cudaFuncSetAttribute(qk_k,     cudaFuncAttributeMaxDynamicSharedMemorySize, SMEM_TOTAL);
        cudaFuncSetAttribute(v_k,      cudaFuncAttributeMaxDynamicSharedMemorySize, SMEM_TOTAL);
        cudaFuncSetAttribute(scores_k, cudaFuncAttributeMaxDynamicSharedMemorySize, SMEM_TOTAL);
        cudaFuncSetAttribute(out_k,    cudaFuncAttributeMaxDynamicSharedMemorySize, SMEM_TOTAL);
        cudaStreamCreateWithFlags(&s2, cudaStreamNonBlocking);
        cudaEventCreateWithFlags(&eFork, cudaEventDisableTiming);
        cudaEventCreateWithFlags(&eJoin, cudaEventDisableTiming);
        inited = 1;
    }

    const int ntot4 = (MTOT*DM + 3*DM*DM)/4;
    cvt_k<<<(ntot4+255)/256, 256>>>((const float4*)x, (const float4*)Wq,
                                    (const float4*)Wk, (const float4*)Wv);

    qk_k<<<dim3(DM/TN, MTOT/TM, 2), NTHR, SMEM_TOTAL>>>();

    // fork: V projection on side stream, concurrent with scores
    cudaEventRecord(eFork, 0);
    cudaStreamWaitEvent(s2, eFork, 0);
    v_k<<<dim3(DM/TN, MTOT/TM), NTHR, SMEM_TOTAL, s2>>>();
    cudaEventRecord(eJoin, s2);

    scores_k<<<dim3(136, NB), NTHR, SMEM_TOTAL>>>();

    // join: out needs both P/PS (default stream) and V (s2)
    cudaStreamWaitEvent(0, eJoin, 0);
    out_k<<<dim3(DM/TN, NB*NMT), NTHR, SMEM_TOTAL>>>(out);
}

// round 14
// speedup vs baseline: 1.1210x; 1.1210x over previous
#include <cuda_runtime.h>
#include <cuda_fp16.h>
#include <stdint.h>

#define SEQL 2048
#define NB   4
#define DM   768
#define MTOT (NB*SEQL)

#define TM 128
#define TN 128
#define BK 32
#define NTHR 128
#define SAH   40
#define SBNTH 40
#define SBNNH 136
#define STAGES 4
#define AS_BYTES (TM*SAH*2)
#define BS_BYTES (TN*SBNTH*2)
#define STAGE_BYTES (AS_BYTES + BS_BYTES)
#define SMEM_TOTAL (STAGES*STAGE_BYTES)   // 81920

#define NMT (SEQL/TM)    // 16 m-tiles per batch

__device__ __half g_X[(size_t)MTOT*DM];
__device__ __half g_W[(size_t)3*DM*DM];
__device__ __half g_Q[(size_t)MTOT*DM];
__device__ __half g_K[(size_t)MTOT*DM];
__device__ __half g_V[(size_t)MTOT*DM];
__device__ __half g_P[(size_t)NB*SEQL*SEQL];
// per-tile partial row sums of exp(S): [b][mt][nt][half][128]
__device__ float  g_PS[(size_t)NB*NMT*NMT*2*128];

static __device__ __forceinline__ void cp16(uint32_t s, const void* g){
    asm volatile("cp.async.cg.shared.global [%0], [%1], 16;" :: "r"(s), "l"(g) : "memory");
}
static __device__ __forceinline__ void ldsm4(uint32_t r[4], uint32_t a){
    asm volatile("ldmatrix.sync.aligned.m8n8.x4.shared.b16 {%0,%1,%2,%3}, [%4];"
        : "=r"(r[0]),"=r"(r[1]),"=r"(r[2]),"=r"(r[3]) : "r"(a));
}
static __device__ __forceinline__ void ldsm4t(uint32_t r[4], uint32_t a){
    asm volatile("ldmatrix.sync.aligned.m8n8.x4.trans.shared.b16 {%0,%1,%2,%3}, [%4];"
        : "=r"(r[0]),"=r"(r[1]),"=r"(r[2]),"=r"(r[3]) : "r"(a));
}
static __device__ __forceinline__ void mma16(float d[4], const uint32_t a[4], uint32_t b0, uint32_t b1){
    asm volatile("mma.sync.aligned.m16n8k16.row.col.f32.f16.f16.f32 "
        "{%0,%1,%2,%3}, {%4,%5,%6,%7}, {%8,%9}, {%0,%1,%2,%3};"
        : "+f"(d[0]),"+f"(d[1]),"+f"(d[2]),"+f"(d[3])
        : "r"(a[0]),"r"(a[1]),"r"(a[2]),"r"(a[3]),"r"(b0),"r"(b1));
}

// ---------------------------------------------------------------------------
// C[128,128] = A[128,kT].op(B); fp16 in, fp32 accum; 4-stage cp.async ring.
// Per-iter order: sync -> ldsm(ks=0) -> cp.async prefetch -> ldsm(ks=1) -> MMAs,
// so the LSU prefetch burst no longer delays the first HMMA of the iteration.
// ---------------------------------------------------------------------------
template<bool BNT>
static __device__ __forceinline__ void gemm_run(
    const __half* __restrict__ A, int lda,
    const __half* __restrict__ B, int ldb,
    int kT, float C[4][8][4])
{
    extern __shared__ char smx[];
    const uint32_t sbase = (uint32_t)__cvta_generic_to_shared(smx);
    const int t = threadIdx.x, lane = t & 31, wid = t >> 5;
    const int wm = (wid & 1) * 64, wn = (wid >> 1) * 64;
    const int lrow = (lane & 7) + ((lane >> 3) & 1) * 8;
    const int loct = lane >> 4;
    const int nIt = kT / BK;

    auto issue = [&](int c){
        const int buf = c & (STAGES-1);
        const uint32_t ab = sbase + buf*STAGE_BYTES;
        const uint32_t bb = ab + AS_BYTES;
        const int k0 = c * BK;
        #pragma unroll
        for (int i=0;i<4;i++){
            int f = t + i*NTHR, row = f>>2, seg = f&3;
            cp16(ab + row*(SAH*2) + seg*16, A + (size_t)row*lda + k0 + seg*8);
        }
        #pragma unroll
        for (int i=0;i<4;i++){
            int f = t + i*NTHR;
            if (BNT){
                int row = f>>2, seg = f&3;
                cp16(bb + row*(SBNTH*2) + seg*16, B + (size_t)row*ldb + k0 + seg*8);
            } else {
                int row = f>>4, seg = f&15;
                cp16(bb + row*(SBNNH*2) + seg*16, B + (size_t)(k0+row)*ldb + seg*8);
            }
        }
        asm volatile("cp.async.commit_group;" ::: "memory");
    };

    #pragma unroll
    for (int s=0; s<STAGES-1; s++) issue(s);

    for (int it=0; it<nIt; it++){
        asm volatile("cp.async.wait_group %0;" :: "n"(STAGES-2) : "memory");
        __syncthreads();

        const uint32_t as = sbase + (it & (STAGES-1))*STAGE_BYTES;
        const uint32_t bs = as + AS_BYTES;

        uint32_t af[2][4][4], bf[2][4][4];
        auto ldA = [&](uint32_t f[4][4], int ks){
            #pragma unroll
            for (int mt=0; mt<4; mt++)
                ldsm4(f[mt], as + (wm + mt*16 + lrow)*(SAH*2) + (ks*16 + loct*8)*2);
        };
        auto ldB = [&](uint32_t f[4][4], int ks){
            #pragma unroll
            for (int n2=0; n2<4; n2++){
                if (BNT)
                    ldsm4(f[n2], bs + (wn + n2*16 + lrow)*(SBNTH*2) + (ks*16 + loct*8)*2);
                else
                    ldsm4t(f[n2], bs + (ks*16 + lrow)*(SBNNH*2) + (wn + n2*16 + loct*8)*2);
            }
        };

        // fragment loads for ks=0 first — they head the critical path
        ldA(af[0], 0); ldB(bf[0], 0);

        // prefetch burst overlaps the ks=0 MMA window instead of preceding it.
        // buffer (it+3)&3 == (it-1)&3 was fully consumed before this iteration's
        // __syncthreads (register dependency of last iteration's MMAs).
        if (it + STAGES-1 < nIt) issue(it + STAGES-1);
        else asm volatile("cp.async.commit_group;" ::: "memory");

        #pragma unroll
        for (int ks=0; ks<2; ks++){
            if (ks == 0){ ldA(af[1], 1); ldB(bf[1], 1); }
            #pragma unroll
            for (int mt=0; mt<4; mt++)
                #pragma unroll
                for (int nt=0; nt<8; nt++){
                    const int n2 = nt>>1, od = nt&1;
                    uint32_t b0 = BNT ? bf[ks][n2][od]   : bf[ks][n2][od*2];
                    uint32_t b1 = BNT ? bf[ks][n2][2+od] : bf[ks][n2][od*2+1];
                    mma16(C[mt][nt], af[ks][mt], b0, b1);
                }
        }
    }
}

static __device__ __forceinline__ void epilogue_h(__half* D, int ldd, float C[4][8][4], float scale)
{
    const int lane = threadIdx.x & 31, wid = threadIdx.x >> 5;
    const int g = lane>>2, tg = lane&3;
    const int wm = (wid&1)*64, wn = (wid>>1)*64;
    #pragma unroll
    for (int mt=0; mt<4; mt++)
        #pragma unroll
        for (int nt=0; nt<8; nt++){
            const int r0 = wm+mt*16+g, c0 = wn+nt*8+2*tg;
            __half2 v0 = __floats2half2_rn(C[mt][nt][0]*scale, C[mt][nt][1]*scale);
            __half2 v1 = __floats2half2_rn(C[mt][nt][2]*scale, C[mt][nt][3]*scale);
            *(__half2*)&D[(size_t)r0*ldd + c0]     = v0;
            *(__half2*)&D[(size_t)(r0+8)*ldd + c0] = v1;
        }
}

static __device__ __forceinline__ void epilogue_p(
    __half* D, int ldd, float C[4][8][4], bool diag, float* __restrict__ psum)
{
    const int lane = threadIdx.x & 31, wid = threadIdx.x >> 5;
    const int g = lane>>2, tg = lane&3;
    const int wm = (wid&1)*64, wn = (wid>>1)*64;
    float rs[4][2] = {};
    #pragma unroll
    for (int mt=0; mt<4; mt++)
        #pragma unroll
        for (int nt=0; nt<8; nt++){
            const int r0 = wm+mt*16+g, c0 = wn+nt*8+2*tg;
            float e0 = __expf(C[mt][nt][0]), e1 = __expf(C[mt][nt][1]);
            float e2 = __expf(C[mt][nt][2]), e3 = __expf(C[mt][nt][3]);
            if (diag){
                if (c0   > r0  ) e0 = 0.0f;
                if (c0+1 > r0  ) e1 = 0.0f;
                if (c0   > r0+8) e2 = 0.0f;
                if (c0+1 > r0+8) e3 = 0.0f;
            }
            *(__half2*)&D[(size_t)r0*ldd + c0]     = __floats2half2_rn(e0, e1);
            *(__half2*)&D[(size_t)(r0+8)*ldd + c0] = __floats2half2_rn(e2, e3);
            rs[mt][0] += e0 + e1;
            rs[mt][1] += e2 + e3;
        }
    #pragma unroll
    for (int mt=0; mt<4; mt++)
        #pragma unroll
        for (int h=0; h<2; h++){
            float v = rs[mt][h];
            v += __shfl_xor_sync(0xffffffffu, v, 1);
            v += __shfl_xor_sync(0xffffffffu, v, 2);
            if (tg == 0)
                psum[(wid>>1)*128 + wm + mt*16 + h*8 + g] = v;
        }
}

static __device__ __forceinline__ void epilogue_fs(float* D, int ldd, float C[4][8][4],
                                                   const float* __restrict__ sInv)
{
    const int lane = threadIdx.x & 31, wid = threadIdx.x >> 5;
    const int g = lane>>2, tg = lane&3;
    const int wm = (wid&1)*64, wn = (wid>>1)*64;
    #pragma unroll
    for (int mt=0; mt<4; mt++){
        const float iv0 = sInv[wm+mt*16+g], iv1 = sInv[wm+mt*16+g+8];
        #pragma unroll
        for (int nt=0; nt<8; nt++){
            const int r0 = wm+mt*16+g, c0 = wn+nt*8+2*tg;
            *(float2*)&D[(size_t)r0*ldd + c0]     = make_float2(C[mt][nt][0]*iv0, C[mt][nt][1]*iv0);
            *(float2*)&D[(size_t)(r0+8)*ldd + c0] = make_float2(C[mt][nt][2]*iv1, C[mt][nt][3]*iv1);
        }
    }
}

// ---------------------------------------------------------------------------
__global__ void __launch_bounds__(256) cvt_k(
    const float4* __restrict__ x, const float4* __restrict__ Wq,
    const float4* __restrict__ Wk, const float4* __restrict__ Wv)
{
    const int nx4 = MTOT*DM/4, nw4 = DM*DM/4;
    int i = blockIdx.x*256 + threadIdx.x;
    const float4* src; __half* dst; int idx;
    if (i < nx4){ src = x; dst = g_X; idx = i; }
    else {
        int j = i - nx4;
        int w = j / nw4; idx = j - w*nw4;
        src = (w==0) ? Wq : (w==1) ? Wk : Wv;
        dst = g_W + (size_t)w*DM*DM;
    }
    float4 v = src[idx];
    __half2 h0 = __floats2half2_rn(v.x, v.y);
    __half2 h1 = __floats2half2_rn(v.z, v.w);
    ((uint2*)dst)[idx] = make_uint2(*(uint32_t*)&h0, *(uint32_t*)&h1);
}

__global__ void __launch_bounds__(NTHR,2) qkv_k()
{
    const int m0 = blockIdx.y*TM, n0 = blockIdx.x*TN;
    const __half* W = g_W + (size_t)blockIdx.z*DM*DM;
    __half*      Cd = (blockIdx.z==0) ? g_Q : (blockIdx.z==1) ? g_K : g_V;
    const float scale = (blockIdx.z==0) ? rsqrtf((float)DM) : 1.0f;

    float C[4][8][4] = {};
    gemm_run<true>(g_X + (size_t)m0*DM, DM, W + (size_t)n0*DM, DM, DM, C);
    epilogue_h(Cd + (size_t)m0*DM + n0, DM, C, scale);
}

__global__ void __launch_bounds__(NTHR,2) scores_k()
{
    const int b = blockIdx.y;
    int i = blockIdx.x;
    int m = (int)((sqrtf(8.0f*i + 1.0f) - 1.0f) * 0.5f);
    while ((m+1)*(m+2)/2 <= i) ++m;
    while (m*(m+1)/2 > i) --m;
    const int n = i - m*(m+1)/2;
    const int m0 = m*TM, n0 = n*TN;

    float C[4][8][4] = {};
    gemm_run<true>(g_Q + ((size_t)b*SEQL + m0)*DM, DM,
                   g_K + ((size_t)b*SEQL + n0)*DM, DM, DM, C);
    epilogue_p(g_P + (size_t)b*SEQL*SEQL + (size_t)m0*SEQL + n0, SEQL, C,
               (m == n),
               g_PS + ((size_t)(b*NMT + m)*NMT + n)*256);
}

// grid (6, 64): y decodes (mtRev, b) -> largest-K tiles first across batches.
__global__ void __launch_bounds__(NTHR,2) out_k(float* __restrict__ out)
{
    const int y = blockIdx.y;
    const int mt = NMT - 1 - (y >> 2);
    const int b  = y & 3;
    const int m0 = mt*TM, n0 = blockIdx.x*TN;

    __shared__ float sInv[128];
    {
        const int r = threadIdx.x;
        const float* ps = g_PS + (size_t)(b*NMT + mt)*NMT*256;
        float s = 0.0f;
        for (int nt=0; nt<=mt; nt++)
            s += ps[nt*256 + r] + ps[nt*256 + 128 + r];
        sInv[r] = 1.0f / s;
    }
    __syncthreads();

    float C[4][8][4] = {};
    gemm_run<false>(g_P + (size_t)b*SEQL*SEQL + (size_t)m0*SEQL, SEQL,
                    g_V + (size_t)b*SEQL*DM + n0, DM, m0 + TM, C);
    epilogue_fs(out + ((size_t)b*SEQL + m0)*DM + n0, DM, C, sInv);
}

// ---------------------------------------------------------------------------
extern "C" void kernel_launch(void* const* d_in, const int* in_sizes, int n_in,
                              void* d_out, int out_size)
{
    const float* x  = (const float*)d_in[0];
    const float* Wq = (const float*)d_in[1];
    const float* Wk = (const float*)d_in[2];
    const float* Wv = (const float*)d_in[3];
    float* out = (float*)d_out;

    static int inited = 0;
    if (!inited){
        cudaFuncSetAttribute(qkv_k,    cudaFuncAttributeMaxDynamicSharedMemorySize, SMEM_TOTAL);
        cudaFuncSetAttribute(scores_k, cudaFuncAttributeMaxDynamicSharedMemorySize, SMEM_TOTAL);
        cudaFuncSetAttribute(out_k,    cudaFuncAttributeMaxDynamicSharedMemorySize, SMEM_TOTAL);
        inited = 1;
    }

    const int ntot4 = (MTOT*DM + 3*DM*DM)/4;
    cvt_k<<<(ntot4+255)/256, 256>>>((const float4*)x, (const float4*)Wq,
                                    (const float4*)Wk, (const float4*)Wv);

    qkv_k   <<<dim3(DM/TN, MTOT/TM, 3),  NTHR, SMEM_TOTAL>>>();
    scores_k<<<dim3(136, NB),            NTHR, SMEM_TOTAL>>>();
    out_k   <<<dim3(DM/TN, NB*NMT),      NTHR, SMEM_TOTAL>>>(out);
}